// round 10
// baseline (speedup 1.0000x reference)
#include <cuda_runtime.h>
#include <cuda_bf16.h>
#include <math_constants.h>

// Problem constants (fixed shapes)
#define B_   8
#define C_   21
#define H_   512
#define W_   512
#define HW_  (H_ * W_)           // 262144 = 2^18
#define HW_SHIFT 18
#define NPIX (B_ * HW_)          // 2097152
#define MAX_M 0.5f
#define S_    30.0f

#define GRID  512
#define TPB   256
#define PPT   16                 // pixels per thread: 512*256*16 = NPIX
#define DEFER 4                  // pixels computed before the grid barrier

// Persistent-kernel state. Zero-initialized at module load; the LAST block of
// every launch resets everything back to zero, so each graph replay starts
// clean (deterministic).
__device__ float        g_counts[C_];
__device__ double       g_loss;
__device__ unsigned int g_arrive;
__device__ unsigned int g_done;

// ---------------------------------------------------------------------------
// Single fused kernel: histogram -> (overlapped) loss main pass -> grid
// barrier -> m_list -> epilogues -> reduction -> finalize -> state reset.
//
// Co-residency: __launch_bounds__(256,4) caps regs at 64 -> 4 CTAs/SM by
// registers; smem ~800B -> 4x148 = 592 >= 512 blocks all resident in wave 1,
// so the software grid barrier cannot deadlock.
//
// Deferred pixels use the raw-max stabilizer identity (validated, rel_err
// 2.7e-6): with A = max(sum_exp - e_l, 0) >= 0 and d = x_l - maxv <= 0,
//   nll = log(A + exp(S*(d - m))) - S*d + S*m
// (exp args <= 0; the target term >= exp(-S*MAX_M) = exp(-15): no over/
// underflow; fmax guards cancellation). Remaining pixels use the exact
// R3 in-loop-margin body (validated, rel_err 1.1e-7).
// ---------------------------------------------------------------------------
__global__ __launch_bounds__(TPB, 4) void fused_kernel(
        const float* __restrict__ pred,
        const int*   __restrict__ target,
        float*       __restrict__ out) {
    __shared__ int   sh[8][C_];
    __shared__ float s_mlist[C_];
    __shared__ float warp_sums[8];

    const int tid  = threadIdx.x;
    const int wid  = tid >> 5;
    const int lane = tid & 31;
    const int base_pix = blockIdx.x * (TPB * PPT);

    for (int i = tid; i < 8 * C_; i += TPB) (&sh[0][0])[i] = 0;
    __syncthreads();

    // ---- Phase A: labels (kept in registers) + histogram ----
    int lab[PPT];
#pragma unroll
    for (int k = 0; k < PPT; k++)
        lab[k] = __ldg(target + base_pix + k * TPB + tid);

#pragma unroll
    for (int k = 0; k < PPT; k++)
        atomicAdd(&sh[wid][lab[k]], 1);
    __syncthreads();

    if (tid < C_) {
        int s = 0;
#pragma unroll
        for (int w = 0; w < 8; w++) s += sh[w][tid];
        atomicAdd(&g_counts[tid], (float)s);   // exact: totals < 2^24
    }
    if (tid == 0) {
        __threadfence();                        // counts visible before arrive
        atomicAdd(&g_arrive, 1u);
    }

    // ---- Deferred main pass: first DEFER pixels, label-independent parts ----
    float A[DEFER], D[DEFER];
#pragma unroll 1
    for (int k = 0; k < DEFER; k++) {
        int n  = base_pix + k * TPB + tid;
        int b  = n >> HW_SHIFT;
        int hw = n & (HW_ - 1);
        const float* base = pred + (size_t)(b * C_) * HW_ + hw;
        int l = lab[k];

        float v[C_];
        float maxv = -CUDART_INF_F, xl = 0.0f;
#pragma unroll
        for (int c = 0; c < C_; c++) {
            float x = __ldg(base + (size_t)c * HW_);
            v[c] = x;
            maxv = fmaxf(maxv, x);
            if (c == l) xl = x;
        }
        float s = 0.0f;
#pragma unroll
        for (int c = 0; c < C_; c++)
            s += __expf(S_ * (v[c] - maxv));

        float el = __expf(S_ * (xl - maxv));
        A[k] = fmaxf(s - el, 0.0f);
        D[k] = xl - maxv;
    }

    // ---- Grid barrier (hidden behind the deferred pass) + m_list ----
    if (tid == 0) {
        while (atomicAdd(&g_arrive, 0u) < GRID) __nanosleep(100);
    }
    __syncthreads();

    if (wid == 0) {
        float mi = 0.0f, m = -CUDART_INF_F;
        if (lane < C_) {
            float c = atomicAdd(&g_counts[lane], 0.0f);  // coherent L2 read
            mi = rsqrtf(sqrtf(c + 1e-4f));
            m  = mi;
        }
#pragma unroll
        for (int o = 16; o > 0; o >>= 1)
            m = fmaxf(m, __shfl_xor_sync(0xffffffffu, m, o));
        if (lane < C_) s_mlist[lane] = mi * (MAX_M / m);
    }
    __syncthreads();

    // ---- Epilogue for deferred pixels ----
    float acc = 0.0f;
#pragma unroll
    for (int k = 0; k < DEFER; k++) {
        float m = s_mlist[lab[k]];
        acc += __logf(A[k] + __expf(S_ * (D[k] - m))) - S_ * D[k] + S_ * m;
    }

    // ---- Remaining pixels: exact R3 in-loop-margin body ----
#pragma unroll 1
    for (int k = DEFER; k < PPT; k++) {
        int n  = base_pix + k * TPB + tid;
        int b  = n >> HW_SHIFT;
        int hw = n & (HW_ - 1);
        const float* base = pred + (size_t)(b * C_) * HW_ + hw;
        int   l = lab[k];
        float m = s_mlist[l];

        float v[C_];
        float maxv = -CUDART_INF_F, vl = 0.0f;
#pragma unroll
        for (int c = 0; c < C_; c++) {
            float x = __ldg(base + (size_t)c * HW_);
            if (c == l) x -= m;
            v[c] = x;
            maxv = fmaxf(maxv, x);
            if (c == l) vl = x;
        }
        float s = 0.0f;
#pragma unroll
        for (int c = 0; c < C_; c++)
            s += __expf(S_ * (v[c] - maxv));

        acc += __logf(s) + S_ * (maxv - vl);
    }

    // ---- Block reduction -> f64 atomic -> fused finalize + state reset ----
#pragma unroll
    for (int o = 16; o > 0; o >>= 1)
        acc += __shfl_xor_sync(0xffffffffu, acc, o);
    if (lane == 0) warp_sums[wid] = acc;
    __syncthreads();

    if (wid == 0) {
        float x = (lane < 8) ? warp_sums[lane] : 0.0f;
#pragma unroll
        for (int o = 4; o > 0; o >>= 1)
            x += __shfl_xor_sync(0xffffffffu, x, o);
        if (lane == 0) {
            atomicAdd(&g_loss, (double)x);
            __threadfence();
            unsigned int done = atomicAdd(&g_done, 1u);
            if (done == GRID - 1) {
                // Every other block has passed the barrier and finished.
                double total = atomicAdd(&g_loss, 0.0);
                out[0] = (float)(total * (1.0 / (double)NPIX));
                // Reset state for the next (graph-replayed) launch.
#pragma unroll
                for (int c = 0; c < C_; c++) g_counts[c] = 0.0f;
                g_loss   = 0.0;
                g_arrive = 0u;
                __threadfence();
                g_done   = 0u;
            }
        }
    }
}

// ---------------------------------------------------------------------------
extern "C" void kernel_launch(void* const* d_in, const int* in_sizes, int n_in,
                              void* d_out, int out_size) {
    const float* pred   = (const float*)d_in[0];
    const int*   target = (const int*)d_in[1];
    float*       out    = (float*)d_out;

    fused_kernel<<<GRID, TPB>>>(pred, target, out);
}

// round 11
// speedup vs baseline: 1.0727x; 1.0727x over previous
#include <cuda_runtime.h>
#include <cuda_bf16.h>
#include <math_constants.h>

// Problem constants (fixed shapes)
#define B_   8
#define C_   21
#define H_   512
#define W_   512
#define HW_  (H_ * W_)           // 262144 = 2^18
#define HW_SHIFT 18
#define NPIX (B_ * HW_)          // 2097152
#define MAX_M 0.5f
#define S_    30.0f

#define GRID  1024
#define TPB   256
#define PPT   8                  // 1024 * 256 * 8 = NPIX
#define DEFER 2                  // pixels streamed before the grid barrier

// Persistent-kernel state. Zero-initialized at module load; the LAST block of
// every launch resets everything, so each graph replay starts clean.
__device__ float        g_counts[C_];
__device__ double       g_loss;
__device__ unsigned int g_arrive;
__device__ unsigned int g_done;

// ---------------------------------------------------------------------------
// Single fused kernel, register-budgeted for FULL occupancy:
//   __launch_bounds__(256, 8) -> regs <= 32 -> 8 CTAs/SM -> 2048 thr/SM.
//   Co-residency: capacity 8*148 = 1184 >= GRID=1024 -> grid barrier is
//   deadlock-free (all blocks resident in wave 1).
//
// Phases: histogram -> arrive -> DEFER label-independent streamed pixels
// (hides barrier skew) -> barrier wait -> m_list -> deferred epilogues ->
// remaining pixels with the exact R3 in-loop-margin body -> reduction ->
// fused finalize -> state reset.
//
// Deferred-pixel identity (validated R10, rel_err 6.4e-7): with raw-max
// stabilizer, A = max(sum_exp - e_l, 0) >= 0, d = x_l - maxv <= 0:
//   nll = log(A + exp(S*(d - m))) - S*d + S*m
// exp args <= 0; target term >= exp(-S*MAX_M) = exp(-15): no over/underflow.
// ---------------------------------------------------------------------------
__global__ __launch_bounds__(TPB, 8) void fused_kernel(
        const float* __restrict__ pred,
        const int*   __restrict__ target,
        float*       __restrict__ out) {
    __shared__ int   sh[8][C_];
    __shared__ float s_mlist[C_];
    __shared__ float warp_sums[8];

    const int tid  = threadIdx.x;
    const int wid  = tid >> 5;
    const int lane = tid & 31;
    const int base_pix = blockIdx.x * (TPB * PPT);   // 2048 pixels per block

    for (int i = tid; i < 8 * C_; i += TPB) (&sh[0][0])[i] = 0;
    __syncthreads();

    // ---- Phase A: histogram of this block's 2048 labels (2 int4/thread) ----
    {
        const int4* t4 = reinterpret_cast<const int4*>(target) + blockIdx.x * 512;
        int4 a0 = __ldg(t4 + tid);
        int4 a1 = __ldg(t4 + 256 + tid);
        atomicAdd(&sh[wid][a0.x], 1);
        atomicAdd(&sh[wid][a0.y], 1);
        atomicAdd(&sh[wid][a0.z], 1);
        atomicAdd(&sh[wid][a0.w], 1);
        atomicAdd(&sh[wid][a1.x], 1);
        atomicAdd(&sh[wid][a1.y], 1);
        atomicAdd(&sh[wid][a1.z], 1);
        atomicAdd(&sh[wid][a1.w], 1);
    }
    __syncthreads();

    if (tid < C_) {
        int s = 0;
#pragma unroll
        for (int w = 0; w < 8; w++) s += sh[w][tid];
        atomicAdd(&g_counts[tid], (float)s);   // exact: totals < 2^24
    }
    if (tid == 0) {
        __threadfence();                        // counts visible before arrive
        atomicAdd(&g_arrive, 1u);
    }

    // ---- Deferred streaming: first DEFER pixels, label-independent parts ----
    float A[DEFER], D[DEFER];
#pragma unroll 1
    for (int k = 0; k < DEFER; k++) {
        int n  = base_pix + k * TPB + tid;
        int b  = n >> HW_SHIFT;
        int hw = n & (HW_ - 1);
        const float* base = pred + (size_t)(b * C_) * HW_ + hw;
        int l = __ldg(target + n);              // L2 hit (just streamed)

        float v[C_];
        float maxv = -CUDART_INF_F, xl = 0.0f;
#pragma unroll
        for (int c = 0; c < C_; c++) {
            float x = __ldg(base + (size_t)c * HW_);
            v[c] = x;
            maxv = fmaxf(maxv, x);
            if (c == l) xl = x;
        }
        float s = 0.0f;
#pragma unroll
        for (int c = 0; c < C_; c++)
            s += __expf(S_ * (v[c] - maxv));

        float el = __expf(S_ * (xl - maxv));
        A[k] = fmaxf(s - el, 0.0f);
        D[k] = xl - maxv;
    }

    // ---- Grid barrier (hidden behind the deferred pass) + m_list ----
    if (tid == 0) {
        while (atomicAdd(&g_arrive, 0u) < GRID) __nanosleep(100);
    }
    __syncthreads();
    __threadfence();   // acquire counts written by other blocks

    if (wid == 0) {
        float mi = 0.0f, m = -CUDART_INF_F;
        if (lane < C_) {
            float c = atomicAdd(&g_counts[lane], 0.0f);  // coherent read
            mi = rsqrtf(sqrtf(c + 1e-4f));
            m  = mi;
        }
#pragma unroll
        for (int o = 16; o > 0; o >>= 1)
            m = fmaxf(m, __shfl_xor_sync(0xffffffffu, m, o));
        if (lane < C_) s_mlist[lane] = mi * (MAX_M / m);
    }
    __syncthreads();

    // ---- Epilogue for deferred pixels (labels reloaded: L2 hits) ----
    float acc = 0.0f;
#pragma unroll
    for (int k = 0; k < DEFER; k++) {
        int   l = __ldg(target + base_pix + k * TPB + tid);
        float m = s_mlist[l];
        acc += __logf(A[k] + __expf(S_ * (D[k] - m))) - S_ * D[k] + S_ * m;
    }

    // ---- Remaining pixels: exact R3 in-loop-margin body ----
#pragma unroll 1
    for (int k = DEFER; k < PPT; k++) {
        int n  = base_pix + k * TPB + tid;
        int b  = n >> HW_SHIFT;
        int hw = n & (HW_ - 1);
        const float* base = pred + (size_t)(b * C_) * HW_ + hw;
        int   l = __ldg(target + n);
        float m = s_mlist[l];

        float v[C_];
        float maxv = -CUDART_INF_F, vl = 0.0f;
#pragma unroll
        for (int c = 0; c < C_; c++) {
            float x = __ldg(base + (size_t)c * HW_);
            if (c == l) x -= m;
            v[c] = x;
            maxv = fmaxf(maxv, x);
            if (c == l) vl = x;
        }
        float s = 0.0f;
#pragma unroll
        for (int c = 0; c < C_; c++)
            s += __expf(S_ * (v[c] - maxv));

        acc += __logf(s) + S_ * (maxv - vl);
    }

    // ---- Block reduction -> f64 atomic -> fused finalize + state reset ----
#pragma unroll
    for (int o = 16; o > 0; o >>= 1)
        acc += __shfl_xor_sync(0xffffffffu, acc, o);
    if (lane == 0) warp_sums[wid] = acc;
    __syncthreads();

    if (wid == 0) {
        float x = (lane < 8) ? warp_sums[lane] : 0.0f;
#pragma unroll
        for (int o = 4; o > 0; o >>= 1)
            x += __shfl_xor_sync(0xffffffffu, x, o);
        if (lane == 0) {
            atomicAdd(&g_loss, (double)x);
            __threadfence();
            unsigned int done = atomicAdd(&g_done, 1u);
            if (done == GRID - 1) {
                // All blocks finished (each passed the barrier first).
                double total = atomicAdd(&g_loss, 0.0);
                out[0] = (float)(total * (1.0 / (double)NPIX));
                // Reset state for the next graph replay.
#pragma unroll
                for (int c = 0; c < C_; c++) g_counts[c] = 0.0f;
                g_loss   = 0.0;
                g_arrive = 0u;
                __threadfence();
                g_done   = 0u;
            }
        }
    }
}

// ---------------------------------------------------------------------------
extern "C" void kernel_launch(void* const* d_in, const int* in_sizes, int n_in,
                              void* d_out, int out_size) {
    const float* pred   = (const float*)d_in[0];
    const int*   target = (const int*)d_in[1];
    float*       out    = (float*)d_out;

    fused_kernel<<<GRID, TPB>>>(pred, target, out);
}